// round 11
// baseline (speedup 1.0000x reference)
#include <cuda_runtime.h>
#include <cuda_bf16.h>
#include <stdint.h>

#define NTOK 4096
#define NEDGE 131072
#define TNUM 8
#define RNUM 16
#define HNUM 8
#define BNUM 21
#define SEEDS 128
#define CAP 96            // per-row edge-list capacity (avg degree = 32, max ~66)
#define BBLK 512          // build grid: 512 blocks x 256 thr = 131072 = NEDGE

// ---------------------------------------------------------------------------
// Device scratch.
// RULE (learned R5/R9): fill_kernel must NEVER write a __device__ global —
// doing so kills the read-only caching of token_type and halves fill BW.
// g_arrive is a MONOTONE epoch counter: never reset by anyone (fixes the R8
// barrier-reuse hang structurally). Each launch consumes one aligned epoch
// of BBLK tickets.
// ---------------------------------------------------------------------------
__device__ int g_cursor[NTOK];         // per-row raw edge count
__device__ int g_elist[NTOK * CAP];    // packed (dst << 4) | rel, per row
__device__ int g_overcnt;              // overflow edge count
__device__ int g_over[NEDGE];          // packed (src << 16) | (dst << 4) | rel
__device__ unsigned g_arrive;          // monotone grid-barrier ticket counter

// ---------------------------------------------------------------------------
__device__ __forceinline__ int bucketize(float dt) {
    float s  = (dt > 0.0f) ? 1.0f : ((dt < 0.0f) ? -1.0f : 0.0f);
    float sl = s * log1pf(fabsf(dt) + 1e-6f);
    float c  = fminf(fmaxf(sl, -5.0f), 5.0f);
    float norm = (c + 5.0f) / (10.0f + 1e-9f);
    int idx = (int)floorf(norm * (float)(BNUM - 1));
    idx = idx < 0 ? 0 : idx;
    idx = idx > (BNUM - 1) ? (BNUM - 1) : idx;
    return idx;
}

// ---------------------------------------------------------------------------
// Merged zero + build (first kernel in the chain).
// All BBLK blocks co-resident in wave 1 (8 blk/SM x 148 SM = 1184 >= 512);
// PDL's grid-wide trigger means fill blocks cannot take SM slots until every
// build block has started -> the spin barrier cannot be starved.
//   Phase A: zero cursors/overcnt; hoist this block's edge loads
//   Phase B: epoch grid barrier (monotone ticket counter, no reset ever)
//   Phase C: one-pass per-row edge-list build
// ---------------------------------------------------------------------------
__global__ __launch_bounds__(256) void build_kernel(
    const int* __restrict__ edge_src,
    const int* __restrict__ edge_dst,
    const int* __restrict__ edge_rel)
{
    cudaTriggerProgrammaticLaunchCompletion();   // fill may begin launching
    const int tid  = threadIdx.x;
    const int gidx = blockIdx.x * 256 + tid;

    // Phase A: zero + hoisted edge loads (overlap load latency with barrier)
    const int s = edge_src[gidx];
    const int d = edge_dst[gidx];
    const int r = edge_rel[gidx];
    if (gidx < NTOK) g_cursor[gidx] = 0;
    if (gidx == 0)   g_overcnt = 0;
    __threadfence();        // zeros visible before any cursor atomics (tiny
    __syncthreads();        // kernel: the R5 L1-flush concern doesn't apply)

    // Phase B: epoch barrier. Tickets of one launch span exactly one aligned
    // BBLK-epoch (launches are stream-serialized), so wait for epoch end.
    if (tid == 0) {
        unsigned ticket = atomicAdd(&g_arrive, 1u);
        unsigned target = ticket - (ticket % BBLK) + BBLK;
        while (atomicAdd(&g_arrive, 0u) < target) { }
    }
    __syncthreads();

    // Phase C: build edge lists (gidx < NEDGE always: 512*256 == NEDGE)
    {
        const int pos = atomicAdd(&g_cursor[s], 1);
        if (pos < CAP) {
            g_elist[s * CAP + pos] = (d << 4) | r;
        } else {
            const int o = atomicAdd(&g_overcnt, 1);
            g_over[o] = (s << 16) | (d << 4) | r;
        }
    }
}

// ---------------------------------------------------------------------------
// Fill kernel (PDL-launched over build): one block per (i, h) row.
// Reads ONLY — no stores to device globals. Phase 1 is independent of build;
// the grid-dependency wait sits after the hot loop, so build hides entirely
// under the ~80us store stream.
// ---------------------------------------------------------------------------
__global__ __launch_bounds__(256) void fill_kernel(
    const int*   __restrict__ token_type,
    const float* __restrict__ time_vec,
    const float* __restrict__ typepair_bias,  // (T, T, H)
    const float* __restrict__ temp_bias,      // (B, H)
    const float* __restrict__ adj_rel_bias,   // (R, H)
    float*       __restrict__ out)            // (H, N, N)
{
    const int i = blockIdx.x;
    const int h = blockIdx.y;
    const int tid = threadIdx.x;

    __shared__ float val8[TNUM];
    __shared__ float tb[BNUM];
    __shared__ float relb[RNUM];

    if (tid < TNUM) {
        const int tt_i = token_type[i];
        val8[tid] = typepair_bias[(tt_i * TNUM + tid) * HNUM + h];
    }
    if (tid < BNUM) tb[tid]   = temp_bias[tid * HNUM + h];
    if (tid < RNUM) relb[tid] = adj_rel_bias[tid * HNUM + h];
    __syncthreads();

    const bool  is_seed = (i < SEEDS);
    const float ti      = time_vec[i];

    float* __restrict__ orow =
        out + ((size_t)h * NTOK + (size_t)i) * (size_t)NTOK;

    // Phase 1: 4096 elements / (256 thr * 4) = 4 float4 stores per thread
    #pragma unroll
    for (int j0 = tid * 4; j0 < NTOK; j0 += 256 * 4) {
        const int4 t4 = *reinterpret_cast<const int4*>(token_type + j0);
        float4 v;
        v.x = val8[t4.x];
        v.y = val8[t4.y];
        v.z = val8[t4.z];
        v.w = val8[t4.w];
        if (is_seed) {
            const float4 tv = *reinterpret_cast<const float4*>(time_vec + j0);
            v.x += tb[bucketize(tv.x - ti)];
            v.y += tb[bucketize(tv.y - ti)];
            v.z += tb[bucketize(tv.z - ti)];
            v.w += tb[bucketize(tv.w - ti)];
        }
        *reinterpret_cast<float4*>(orow + j0) = v;
    }
    __syncthreads();               // row fully stored before RMW

    cudaGridDependencySynchronize();   // build's cursors/lists now visible

    // Phase 2a: this row's edges — L2-hit atomics into the fresh row
    const int count = min(g_cursor[i], CAP);
    for (int e = tid; e < count; e += 256) {
        const int p = g_elist[i * CAP + e];
        atomicAdd(orow + (p >> 4), relb[p & 15]);
    }

    // Phase 2b: overflow entries for this row (normally g_overcnt == 0)
    const int on = g_overcnt;
    for (int e = tid; e < on; e += 256) {
        const int p = g_over[e];
        if ((p >> 16) == i)
            atomicAdd(orow + ((p >> 4) & 0xFFF), relb[p & 15]);
    }
}

// ---------------------------------------------------------------------------
// Launch: build -> (PDL) -> fill. Two kernels total.
// ---------------------------------------------------------------------------
extern "C" void kernel_launch(void* const* d_in, const int* in_sizes, int n_in,
                              void* d_out, int out_size)
{
    const int*   token_type    = (const int*)  d_in[0];
    const int*   edge_src      = (const int*)  d_in[1];
    const int*   edge_dst      = (const int*)  d_in[2];
    const int*   edge_rel      = (const int*)  d_in[3];
    const float* time_vec      = (const float*)d_in[4];
    const float* adj_rel_bias  = (const float*)d_in[n_in - 3];
    const float* typepair_bias = (const float*)d_in[n_in - 2];
    const float* temp_bias     = (const float*)d_in[n_in - 1];
    float* out = (float*)d_out;

    cudaLaunchAttribute pdl[1];
    pdl[0].id = cudaLaunchAttributeProgrammaticStreamSerialization;
    pdl[0].val.programmaticStreamSerializationAllowed = 1;

    // build: plain launch (head of chain)
    build_kernel<<<BBLK, 256>>>(edge_src, edge_dst, edge_rel);

    // fill: PDL over build
    {
        cudaLaunchConfig_t cfg = {};
        cfg.gridDim  = dim3(NTOK, HNUM);
        cfg.blockDim = dim3(256);
        cfg.attrs    = pdl;
        cfg.numAttrs = 1;
        cfg.stream   = 0;
        cudaLaunchKernelEx(&cfg, fill_kernel, token_type, time_vec,
                           typepair_bias, temp_bias, adj_rel_bias, out);
    }
}

// round 12
// speedup vs baseline: 1.0136x; 1.0136x over previous
#include <cuda_runtime.h>
#include <cuda_bf16.h>
#include <stdint.h>

#define NTOK 4096
#define NEDGE 131072
#define TNUM 8
#define RNUM 16
#define HNUM 8
#define BNUM 21
#define SEEDS 128
#define CAP 96            // per-row edge-list capacity (avg degree = 32, max ~66)

// ---------------------------------------------------------------------------
// Device scratch.
// RULE (learned R5/R9): fill_kernel must NEVER write a __device__ global —
// doing so kills the read-only caching of token_type and halves fill BW.
// g_zero_region = [cursor[NTOK] | overcnt] — one contiguous block wiped by a
// single graph memset node each launch (cheaper than a zero kernel, R11/R12).
// ---------------------------------------------------------------------------
__device__ int g_zero_region[NTOK + 1];   // [0..NTOK) cursors, [NTOK] overcnt
__device__ int g_elist[NTOK * CAP];       // packed (dst << 4) | rel, per row
__device__ int g_over[NEDGE];             // packed (src << 16) | (dst << 4) | rel

#define g_cursor  g_zero_region
#define g_overcnt g_zero_region[NTOK]

// ---------------------------------------------------------------------------
__device__ __forceinline__ int bucketize(float dt) {
    float s  = (dt > 0.0f) ? 1.0f : ((dt < 0.0f) ? -1.0f : 0.0f);
    float sl = s * log1pf(fabsf(dt) + 1e-6f);
    float c  = fminf(fmaxf(sl, -5.0f), 5.0f);
    float norm = (c + 5.0f) / (10.0f + 1e-9f);
    int idx = (int)floorf(norm * (float)(BNUM - 1));
    idx = idx < 0 ? 0 : idx;
    idx = idx > (BNUM - 1) ? (BNUM - 1) : idx;
    return idx;
}

// ---------------------------------------------------------------------------
// One-pass per-row edge-list build. Runs stream-ordered after the memset.
// Fires the PDL trigger at entry so fill can begin launching immediately;
// fill's grid-dependency sync (after its hot loop) provides the real
// ordering for cursor/list visibility.
// ---------------------------------------------------------------------------
__global__ __launch_bounds__(256) void build_kernel(
    const int* __restrict__ edge_src,
    const int* __restrict__ edge_dst,
    const int* __restrict__ edge_rel)
{
    cudaTriggerProgrammaticLaunchCompletion();   // let fill start launching
    const int e = blockIdx.x * blockDim.x + threadIdx.x;
    if (e >= NEDGE) return;
    const int s = edge_src[e];
    const int d = edge_dst[e];
    const int r = edge_rel[e];
    const int pos = atomicAdd(&g_cursor[s], 1);
    if (pos < CAP) {
        g_elist[s * CAP + pos] = (d << 4) | r;
    } else {
        const int o = atomicAdd(&g_overcnt, 1);
        g_over[o] = (s << 16) | (d << 4) | r;
    }
}

// ---------------------------------------------------------------------------
// Fill kernel (PDL-launched over build): one block per (i, h) row.
// Reads ONLY — no stores to device globals. Phase 1 is independent of build;
// the grid-dependency wait sits after the hot loop, so memset+build hide
// almost entirely under the ~80us store stream.
//   Phase 1:  direct coalesced float4 stores (~80us, ~6.7 TB/s — the roofline).
//   Phase 2a: this row's edges via L2-hit atomicAdd into the fresh row.
//   Phase 2b: overflow entries (normally zero).
// ---------------------------------------------------------------------------
__global__ __launch_bounds__(256) void fill_kernel(
    const int*   __restrict__ token_type,
    const float* __restrict__ time_vec,
    const float* __restrict__ typepair_bias,  // (T, T, H)
    const float* __restrict__ temp_bias,      // (B, H)
    const float* __restrict__ adj_rel_bias,   // (R, H)
    float*       __restrict__ out)            // (H, N, N)
{
    const int i = blockIdx.x;
    const int h = blockIdx.y;
    const int tid = threadIdx.x;

    __shared__ float val8[TNUM];
    __shared__ float tb[BNUM];
    __shared__ float relb[RNUM];

    if (tid < TNUM) {
        const int tt_i = token_type[i];
        val8[tid] = typepair_bias[(tt_i * TNUM + tid) * HNUM + h];
    }
    if (tid < BNUM) tb[tid]   = temp_bias[tid * HNUM + h];
    if (tid < RNUM) relb[tid] = adj_rel_bias[tid * HNUM + h];
    __syncthreads();

    const bool  is_seed = (i < SEEDS);
    const float ti      = time_vec[i];

    float* __restrict__ orow =
        out + ((size_t)h * NTOK + (size_t)i) * (size_t)NTOK;

    // Phase 1: 4096 elements / (256 thr * 4) = 4 float4 stores per thread
    #pragma unroll
    for (int j0 = tid * 4; j0 < NTOK; j0 += 256 * 4) {
        const int4 t4 = *reinterpret_cast<const int4*>(token_type + j0);
        float4 v;
        v.x = val8[t4.x];
        v.y = val8[t4.y];
        v.z = val8[t4.z];
        v.w = val8[t4.w];
        if (is_seed) {
            const float4 tv = *reinterpret_cast<const float4*>(time_vec + j0);
            v.x += tb[bucketize(tv.x - ti)];
            v.y += tb[bucketize(tv.y - ti)];
            v.z += tb[bucketize(tv.z - ti)];
            v.w += tb[bucketize(tv.w - ti)];
        }
        *reinterpret_cast<float4*>(orow + j0) = v;
    }
    __syncthreads();               // row fully stored before RMW

    cudaGridDependencySynchronize();   // build's cursors/lists now visible

    // Phase 2a: this row's edges — L2-hit atomics into the fresh row
    const int count = min(g_cursor[i], CAP);
    for (int e = tid; e < count; e += 256) {
        const int p = g_elist[i * CAP + e];
        atomicAdd(orow + (p >> 4), relb[p & 15]);
    }

    // Phase 2b: overflow entries for this row (normally g_overcnt == 0)
    const int on = g_overcnt;
    for (int e = tid; e < on; e += 256) {
        const int p = g_over[e];
        if ((p >> 16) == i)
            atomicAdd(orow + ((p >> 4) & 0xFFF), relb[p & 15]);
    }
}

// ---------------------------------------------------------------------------
// Launch: memset (graph node) -> build -> (PDL) -> fill.
// ---------------------------------------------------------------------------
extern "C" void kernel_launch(void* const* d_in, const int* in_sizes, int n_in,
                              void* d_out, int out_size)
{
    const int*   token_type    = (const int*)  d_in[0];
    const int*   edge_src      = (const int*)  d_in[1];
    const int*   edge_dst      = (const int*)  d_in[2];
    const int*   edge_rel      = (const int*)  d_in[3];
    const float* time_vec      = (const float*)d_in[4];
    const float* adj_rel_bias  = (const float*)d_in[n_in - 3];
    const float* typepair_bias = (const float*)d_in[n_in - 2];
    const float* temp_bias     = (const float*)d_in[n_in - 1];
    float* out = (float*)d_out;

    // Zero cursors + overcnt via a graph memset node (cheaper than a kernel)
    void* zr = nullptr;
    cudaGetSymbolAddress(&zr, g_zero_region);
    cudaMemsetAsync(zr, 0, (NTOK + 1) * sizeof(int), 0);

    // build: stream-ordered after the memset
    build_kernel<<<(NEDGE + 255) / 256, 256>>>(edge_src, edge_dst, edge_rel);

    // fill: PDL over build
    cudaLaunchAttribute pdl[1];
    pdl[0].id = cudaLaunchAttributeProgrammaticStreamSerialization;
    pdl[0].val.programmaticStreamSerializationAllowed = 1;

    cudaLaunchConfig_t cfg = {};
    cfg.gridDim  = dim3(NTOK, HNUM);
    cfg.blockDim = dim3(256);
    cfg.attrs    = pdl;
    cfg.numAttrs = 1;
    cfg.stream   = 0;
    cudaLaunchKernelEx(&cfg, fill_kernel, token_type, time_vec,
                       typepair_bias, temp_bias, adj_rel_bias, out);
}